// round 11
// baseline (speedup 1.0000x reference)
#include <cuda_runtime.h>
#include <cuda_bf16.h>

// Sparsemax over rows: x, mask are [8192, 4096] fp32; out fp32 same shape.
// z = (mask ? x : NEG_BIG) * 2 ; tau solves sum(relu(z - tau)) = 1 ;
// out = relu(z - tau)  (mask multiply implied: masked z is hugely negative).
//
// R11: tau >= zmax - 1 => support lies in {z > zmax - 1} (typically 1-6
// elements block-wide, <1 per warp). Ballot-based gather: a thread holding
// EXACTLY ONE candidate takes slot popc(ballot & below). A thread holding
// >=2 (rare: two support elems in one 16-elem strip, ~1% of rows) marks the
// warp overflowed -> proven block-Newton fallback (block-uniform decision).
// Two __syncthreads per row; Newton itself is warp-local and barrier-free.

#define ROWS 8192
#define COLS 4096
#define THREADS 256
#define NWARPS (THREADS / 32)
#define ELEMS (COLS / THREADS)   // 16 floats per thread
#define VEC (ELEMS / 4)          // 4 float4 per thread
#define WCAP 16                  // candidate slots per warp
#define CAP (NWARPS * WCAP)      // 128 total (4 per lane)

__global__ __launch_bounds__(THREADS, 5)
void sparsemax_kernel(const float* __restrict__ x,
                      const float* __restrict__ m,
                      float* __restrict__ out) {
    const int row = blockIdx.x;
    const int t   = threadIdx.x;
    const int lane = t & 31;
    const int wid  = t >> 5;

    const float4* __restrict__ xr = reinterpret_cast<const float4*>(x + (size_t)row * COLS);
    const float4* __restrict__ mr = reinterpret_cast<const float4*>(m + (size_t)row * COLS);
    float4* __restrict__ orow     = reinterpret_cast<float4*>(out + (size_t)row * COLS);

    __shared__ float shmax[NWARPS];
    __shared__ int   wovf[NWARPS];    // warp overflow flags
    __shared__ float cand[CAP];
    __shared__ float fs[2][NWARPS];   // fallback double-buffer (sum)
    __shared__ int   fc[2][NWARPS];   // fallback double-buffer (count)

    // ---- Front-batch ALL loads (8 x LDG.128 in flight per thread) ----
    float4 xv[VEC];
    float4 mv[VEC];
#pragma unroll
    for (int v = 0; v < VEC; v++) xv[v] = xr[t + v * THREADS];
#pragma unroll
    for (int v = 0; v < VEC; v++) mv[v] = mr[t + v * THREADS];

    // Pre-initialize this warp's candidate segment (ordered by barrier 1).
    if (lane < WCAP) cand[wid * WCAP + lane] = -3.0e38f;

    // ---- Apply mask + temperature, track local max ----
    float z[ELEMS];
    float vmax = -3.0e38f;
    const float NEGZ = -9999999.9f * 2.0f;  // masked value after temperature
#pragma unroll
    for (int v = 0; v < VEC; v++) {
        float z0 = (mv[v].x != 0.0f) ? (xv[v].x * 2.0f) : NEGZ;
        float z1 = (mv[v].y != 0.0f) ? (xv[v].y * 2.0f) : NEGZ;
        float z2 = (mv[v].z != 0.0f) ? (xv[v].z * 2.0f) : NEGZ;
        float z3 = (mv[v].w != 0.0f) ? (xv[v].w * 2.0f) : NEGZ;
        z[v * 4 + 0] = z0;
        z[v * 4 + 1] = z1;
        z[v * 4 + 2] = z2;
        z[v * 4 + 3] = z3;
        vmax = fmaxf(vmax, fmaxf(fmaxf(z0, z1), fmaxf(z2, z3)));
    }

    // ---- Block max reduction ----
#pragma unroll
    for (int o = 16; o > 0; o >>= 1)
        vmax = fmaxf(vmax, __shfl_xor_sync(0xFFFFFFFFu, vmax, o));
    if (lane == 0) shmax[wid] = vmax;
    __syncthreads();                       // barrier 1
    float zmax = -3.0e38f;
#pragma unroll
    for (int i = 0; i < NWARPS; i++) zmax = fmaxf(zmax, shmax[i]);

    const float T0 = zmax - 1.0f;

    // ---- Ballot gather: count candidates + remember the (single) value ----
    int   lc = 0;
    float cv = -3.0e38f;
#pragma unroll
    for (int e = 0; e < ELEMS; e++) {
        if (z[e] > T0) { lc++; cv = z[e]; }
    }
    const unsigned has  = __ballot_sync(0xFFFFFFFFu, lc > 0);
    const unsigned multi = __ballot_sync(0xFFFFFFFFu, lc > 1);
    if (lane == 0) wovf[wid] = (multi != 0u) ? 1 : 0;
    if (lc == 1) {
        int slot = __popc(has & ((1u << lane) - 1u));   // < 32 <= ok vs WCAP=16? see below
        if (slot < WCAP) cand[wid * WCAP + slot] = cv;
        else if (lane == 0) { /* unreachable when multi==0 and slot>=WCAP handled below */ }
        if (slot >= WCAP && lane == lane) { /* overflow by count */ }
    }
    // Count-overflow (more than WCAP single-candidate lanes) -> mark overflow.
    if (lane == 0 && __popc(has) > WCAP) wovf[wid] = 1;
    __syncthreads();                       // barrier 2 (last barrier)

    bool ovf = false;
#pragma unroll
    for (int i = 0; i < NWARPS; i++) ovf |= (wovf[i] != 0);

    float tau;
    if (!ovf) {
        // ---- Warp-local Newton (every warp redundantly; identical tau) ----
        float c0 = cand[lane +  0];
        float c1 = cand[lane + 32];
        float c2 = cand[lane + 64];
        float c3 = cand[lane + 96];

        float T = T0;
#pragma unroll 1
        for (int it = 0; it < 32; ++it) {
            float s = 0.0f, c = 0.0f;
            float d;
            d = c0 - T; if (d > 0.0f) { s += d; c += 1.0f; }
            d = c1 - T; if (d > 0.0f) { s += d; c += 1.0f; }
            d = c2 - T; if (d > 0.0f) { s += d; c += 1.0f; }
            d = c3 - T; if (d > 0.0f) { s += d; c += 1.0f; }
#pragma unroll
            for (int o = 16; o > 0; o >>= 1) {
                s += __shfl_xor_sync(0xFFFFFFFFu, s, o);
                c += __shfl_xor_sync(0xFFFFFFFFu, c, o);
            }
            if (c < 0.5f) break;           // can't happen (zmax is a candidate)
            float delta = __fdividef(s - 1.0f, c);
            T += delta;
            if (fabsf(delta) < 1e-6f) break;
        }
        tau = T;
    } else {
        // ---- Fallback: proven block-Newton (block-uniform branch) ----
        float T = T0;
#pragma unroll 1
        for (int it = 0; it < 32; ++it) {
            const int b = it & 1;
            float s = 0.0f;
            int   c = 0;
#pragma unroll
            for (int e = 0; e < ELEMS; e++) {
                float d = z[e] - T;
                if (d > 0.0f) { s += d; c += 1; }
            }
#pragma unroll
            for (int o = 16; o > 0; o >>= 1) {
                s += __shfl_xor_sync(0xFFFFFFFFu, s, o);
                c += __shfl_xor_sync(0xFFFFFFFFu, c, o);
            }
            if (lane == 0) { fs[b][wid] = s; fc[b][wid] = c; }
            __syncthreads();
            float S = 0.0f;
            int   C = 0;
#pragma unroll
            for (int i = 0; i < NWARPS; i++) { S += fs[b][i]; C += fc[b][i]; }

            if (C == 0) break;
            float delta = __fdividef(S - 1.0f, (float)C);
            T += delta;
            if (fabsf(delta) < 1e-6f) break;
        }
        tau = T;
    }

    // ---- Output: relu(z - tau). Masked entries are ~-2e7, relu -> 0. ----
#pragma unroll
    for (int v = 0; v < VEC; v++) {
        float4 ov;
        ov.x = fmaxf(0.0f, z[v * 4 + 0] - tau);
        ov.y = fmaxf(0.0f, z[v * 4 + 1] - tau);
        ov.z = fmaxf(0.0f, z[v * 4 + 2] - tau);
        ov.w = fmaxf(0.0f, z[v * 4 + 3] - tau);
        orow[t + v * THREADS] = ov;
    }
}

extern "C" void kernel_launch(void* const* d_in, const int* in_sizes, int n_in,
                              void* d_out, int out_size) {
    const float* x = (const float*)d_in[0];
    const float* m = (const float*)d_in[1];
    float* out = (float*)d_out;
    sparsemax_kernel<<<ROWS, THREADS>>>(x, m, out);
}

// round 12
// speedup vs baseline: 1.0046x; 1.0046x over previous
#include <cuda_runtime.h>
#include <cuda_bf16.h>

// Sparsemax over rows: x, mask are [8192, 4096] fp32; out fp32 same shape.
// z = (mask ? x : NEG_BIG) * 2 ; tau solves sum(relu(z - tau)) = 1 ;
// out = relu(z - tau)  (mask multiply implied: masked z is hugely negative).
//
// R12: ONE __syncthreads per row. Each warp gathers candidates against its
// OWN warp max (zmax_w - 1): since zmax_w <= zmax, this is a superset of the
// true support within that warp; sub-threshold extras contribute 0 to every
// Newton evaluation (relu), so correctness is preserved. After the single
// barrier, every warp computes the global max from shmax and runs a
// barrier-free warp-local Newton over the 128 gathered slots (identical tau
// in all warps). Block-uniform fallback to the proven block-Newton on
// overflow (slot pressure), which is data-rare.

#define ROWS 8192
#define COLS 4096
#define THREADS 256
#define NWARPS (THREADS / 32)
#define ELEMS (COLS / THREADS)   // 16 floats per thread
#define VEC (ELEMS / 4)          // 4 float4 per thread
#define WCAP 16                  // candidate slots per warp
#define CAP (NWARPS * WCAP)      // 128 total (4 per lane)

__global__ __launch_bounds__(THREADS, 5)
void sparsemax_kernel(const float* __restrict__ x,
                      const float* __restrict__ m,
                      float* __restrict__ out) {
    const int row = blockIdx.x;
    const int t   = threadIdx.x;
    const int lane = t & 31;
    const int wid  = t >> 5;

    const float4* __restrict__ xr = reinterpret_cast<const float4*>(x + (size_t)row * COLS);
    const float4* __restrict__ mr = reinterpret_cast<const float4*>(m + (size_t)row * COLS);
    float4* __restrict__ orow     = reinterpret_cast<float4*>(out + (size_t)row * COLS);

    __shared__ float shmax[NWARPS];
    __shared__ int   wovf[NWARPS];    // warp overflow flags
    __shared__ float cand[CAP];
    __shared__ float fs[2][NWARPS];   // fallback double-buffer (sum)
    __shared__ int   fc[2][NWARPS];   // fallback double-buffer (count)

    // ---- Front-batch ALL loads (8 x LDG.128 in flight per thread) ----
    float4 xv[VEC];
    float4 mv[VEC];
#pragma unroll
    for (int v = 0; v < VEC; v++) xv[v] = xr[t + v * THREADS];
#pragma unroll
    for (int v = 0; v < VEC; v++) mv[v] = mr[t + v * THREADS];

    // Pre-initialize this warp's PRIVATE candidate segment. Ordering vs the
    // gather writes below is warp-internal -> __syncwarp, no block barrier.
    if (lane < WCAP) cand[wid * WCAP + lane] = -3.0e38f;

    // ---- Apply mask + temperature, track local max ----
    float z[ELEMS];
    float vmax = -3.0e38f;
    const float NEGZ = -9999999.9f * 2.0f;  // masked value after temperature
#pragma unroll
    for (int v = 0; v < VEC; v++) {
        float z0 = (mv[v].x != 0.0f) ? (xv[v].x * 2.0f) : NEGZ;
        float z1 = (mv[v].y != 0.0f) ? (xv[v].y * 2.0f) : NEGZ;
        float z2 = (mv[v].z != 0.0f) ? (xv[v].z * 2.0f) : NEGZ;
        float z3 = (mv[v].w != 0.0f) ? (xv[v].w * 2.0f) : NEGZ;
        z[v * 4 + 0] = z0;
        z[v * 4 + 1] = z1;
        z[v * 4 + 2] = z2;
        z[v * 4 + 3] = z3;
        vmax = fmaxf(vmax, fmaxf(fmaxf(z0, z1), fmaxf(z2, z3)));
    }

    // ---- Warp max (no block barrier) ----
#pragma unroll
    for (int o = 16; o > 0; o >>= 1)
        vmax = fmaxf(vmax, __shfl_xor_sync(0xFFFFFFFFu, vmax, o));
    if (lane == 0) shmax[wid] = vmax;

    // ---- Warp-local candidate gather vs WARP threshold (superset of true) --
    const float T0w = vmax - 1.0f;   // vmax is warp-uniform after the shuffle
    __syncwarp();                    // order segment init before gather writes

    int   lc = 0;
    float cv = -3.0e38f;
#pragma unroll
    for (int e = 0; e < ELEMS; e++) {
        if (z[e] > T0w) { lc++; cv = z[e]; }
    }
    const unsigned has   = __ballot_sync(0xFFFFFFFFu, lc > 0);
    const unsigned multi = __ballot_sync(0xFFFFFFFFu, lc > 1);
    if (lc == 1) {
        int slot = __popc(has & ((1u << lane) - 1u));
        if (slot < WCAP) cand[wid * WCAP + slot] = cv;
    }
    if (lane == 0)
        wovf[wid] = (multi != 0u || __popc(has) > WCAP) ? 1 : 0;

    __syncthreads();                 // THE single block barrier per row

    // ---- Global max + overflow check (all warps, from shared) ----
    float zmax = -3.0e38f;
    bool ovf = false;
#pragma unroll
    for (int i = 0; i < NWARPS; i++) {
        zmax = fmaxf(zmax, shmax[i]);
        ovf |= (wovf[i] != 0);
    }
    const float T0 = zmax - 1.0f;

    float tau;
    if (!ovf) {
        // ---- Warp-local Newton (every warp redundantly; identical tau).
        //      Sub-threshold candidates (< T0) contribute 0 always. ----
        float c0 = cand[lane +  0];
        float c1 = cand[lane + 32];
        float c2 = cand[lane + 64];
        float c3 = cand[lane + 96];

        float T = T0;
#pragma unroll 1
        for (int it = 0; it < 32; ++it) {
            float s = 0.0f, c = 0.0f;
            float d;
            d = c0 - T; if (d > 0.0f) { s += d; c += 1.0f; }
            d = c1 - T; if (d > 0.0f) { s += d; c += 1.0f; }
            d = c2 - T; if (d > 0.0f) { s += d; c += 1.0f; }
            d = c3 - T; if (d > 0.0f) { s += d; c += 1.0f; }
#pragma unroll
            for (int o = 16; o > 0; o >>= 1) {
                s += __shfl_xor_sync(0xFFFFFFFFu, s, o);
                c += __shfl_xor_sync(0xFFFFFFFFu, c, o);
            }
            if (c < 0.5f) break;           // can't happen (zmax is a candidate)
            float delta = __fdividef(s - 1.0f, c);
            T += delta;
            if (fabsf(delta) < 1e-6f) break;
        }
        tau = T;
    } else {
        // ---- Fallback: proven block-Newton (block-uniform branch) ----
        float T = T0;
#pragma unroll 1
        for (int it = 0; it < 32; ++it) {
            const int b = it & 1;
            float s = 0.0f;
            int   c = 0;
#pragma unroll
            for (int e = 0; e < ELEMS; e++) {
                float d = z[e] - T;
                if (d > 0.0f) { s += d; c += 1; }
            }
#pragma unroll
            for (int o = 16; o > 0; o >>= 1) {
                s += __shfl_xor_sync(0xFFFFFFFFu, s, o);
                c += __shfl_xor_sync(0xFFFFFFFFu, c, o);
            }
            if (lane == 0) { fs[b][wid] = s; fc[b][wid] = c; }
            __syncthreads();
            float S = 0.0f;
            int   C = 0;
#pragma unroll
            for (int i = 0; i < NWARPS; i++) { S += fs[b][i]; C += fc[b][i]; }

            if (C == 0) break;
            float delta = __fdividef(S - 1.0f, (float)C);
            T += delta;
            if (fabsf(delta) < 1e-6f) break;
        }
        tau = T;
    }

    // ---- Output: relu(z - tau). Masked entries are ~-2e7, relu -> 0. ----
#pragma unroll
    for (int v = 0; v < VEC; v++) {
        float4 ov;
        ov.x = fmaxf(0.0f, z[v * 4 + 0] - tau);
        ov.y = fmaxf(0.0f, z[v * 4 + 1] - tau);
        ov.z = fmaxf(0.0f, z[v * 4 + 2] - tau);
        ov.w = fmaxf(0.0f, z[v * 4 + 3] - tau);
        orow[t + v * THREADS] = ov;
    }
}

extern "C" void kernel_launch(void* const* d_in, const int* in_sizes, int n_in,
                              void* d_out, int out_size) {
    const float* x = (const float*)d_in[0];
    const float* m = (const float*)d_in[1];
    float* out = (float*)d_out;
    sparsemax_kernel<<<ROWS, THREADS>>>(x, m, out);
}

// round 13
// speedup vs baseline: 1.0112x; 1.0066x over previous
#include <cuda_runtime.h>
#include <cuda_bf16.h>

// Sparsemax over rows: x, mask are [8192, 4096] fp32; out fp32 same shape.
// z = (mask ? x : NEG_BIG) * 2 ; tau solves sum(relu(z - tau)) = 1 ;
// out = relu(z - tau)  (mask multiply implied: masked z is hugely negative).
//
// FINAL (== R9, best measured wall 62.6 us; dram ~81-83% = streaming ceiling
// for this 2R:1W pattern on GB300):
//   - front-batched 8x LDG.128 per thread for MLP
//   - tau >= zmax-1 => support lies in {z > zmax-1} (typically 2-6 elems);
//     gather candidates to shared via deterministic prefix-scan (2 barriers),
//     then EVERY warp redundantly runs a barrier-free warp-local Newton
//     (identical tau in all warps)
//   - __fdividef on the Newton step
//   - proven block-Newton fallback if candidates overflow (block-uniform)

#define ROWS 8192
#define COLS 4096
#define THREADS 256
#define NWARPS (THREADS / 32)
#define ELEMS (COLS / THREADS)   // 16 floats per thread
#define VEC (ELEMS / 4)          // 4 float4 per thread
#define CAP 128                  // candidate buffer (4 per lane)

__global__ __launch_bounds__(THREADS, 5)
void sparsemax_kernel(const float* __restrict__ x,
                      const float* __restrict__ m,
                      float* __restrict__ out) {
    const int row = blockIdx.x;
    const int t   = threadIdx.x;
    const int lane = t & 31;
    const int wid  = t >> 5;

    const float4* __restrict__ xr = reinterpret_cast<const float4*>(x + (size_t)row * COLS);
    const float4* __restrict__ mr = reinterpret_cast<const float4*>(m + (size_t)row * COLS);
    float4* __restrict__ orow     = reinterpret_cast<float4*>(out + (size_t)row * COLS);

    __shared__ float shs[2][NWARPS];   // reduce scratch (max / fallback s)
    __shared__ int   shc[2][NWARPS];   // warp candidate counts / fallback c
    __shared__ float cand[CAP];        // gathered candidates

    // ---- Front-batch ALL loads (8 x LDG.128 in flight per thread) ----
    float4 xv[VEC];
    float4 mv[VEC];
#pragma unroll
    for (int v = 0; v < VEC; v++) xv[v] = xr[t + v * THREADS];
#pragma unroll
    for (int v = 0; v < VEC; v++) mv[v] = mr[t + v * THREADS];

    // ---- Apply mask + temperature, track local max ----
    float z[ELEMS];
    float vmax = -3.0e38f;
    const float NEGZ = -9999999.9f * 2.0f;  // masked value after temperature
#pragma unroll
    for (int v = 0; v < VEC; v++) {
        float z0 = (mv[v].x != 0.0f) ? (xv[v].x * 2.0f) : NEGZ;
        float z1 = (mv[v].y != 0.0f) ? (xv[v].y * 2.0f) : NEGZ;
        float z2 = (mv[v].z != 0.0f) ? (xv[v].z * 2.0f) : NEGZ;
        float z3 = (mv[v].w != 0.0f) ? (xv[v].w * 2.0f) : NEGZ;
        z[v * 4 + 0] = z0;
        z[v * 4 + 1] = z1;
        z[v * 4 + 2] = z2;
        z[v * 4 + 3] = z3;
        vmax = fmaxf(vmax, fmaxf(fmaxf(z0, z1), fmaxf(z2, z3)));
    }

    // ---- Block max reduction ----
#pragma unroll
    for (int o = 16; o > 0; o >>= 1)
        vmax = fmaxf(vmax, __shfl_xor_sync(0xFFFFFFFFu, vmax, o));
    if (lane == 0) shs[0][wid] = vmax;
    __syncthreads();                       // barrier 1
    float zmax = -3.0e38f;
#pragma unroll
    for (int i = 0; i < NWARPS; i++) zmax = fmaxf(zmax, shs[0][i]);

    const float T0 = zmax - 1.0f;

    // ---- Count candidates (z > T0) per thread; deterministic warp scan ----
    int lc = 0;
#pragma unroll
    for (int e = 0; e < ELEMS; e++) lc += (z[e] > T0) ? 1 : 0;

    int inc = lc;                          // inclusive prefix over lanes
#pragma unroll
    for (int o = 1; o < 32; o <<= 1) {
        int v = __shfl_up_sync(0xFFFFFFFFu, inc, o);
        if (lane >= o) inc += v;
    }
    const int excl = inc - lc;
    const int wtot = __shfl_sync(0xFFFFFFFFu, inc, 31);
    if (lane == 31) shc[1][wid] = wtot;
    __syncthreads();                       // barrier 2

    int base = 0, n = 0;
#pragma unroll
    for (int i = 0; i < NWARPS; i++) {
        int w = shc[1][i];
        if (i < wid) base += w;
        n += w;
    }

    float tau;
    if (n <= CAP) {
        // ---- Write candidates at deterministic slots ----
        int off = base + excl;
#pragma unroll
        for (int e = 0; e < ELEMS; e++) {
            if (z[e] > T0) cand[off++] = z[e];
        }
        __syncthreads();                   // barrier 3 (last barrier)

        // ---- Warp-local Newton (every warp redundantly; identical tau) ----
        float c0 = (lane +  0 < n) ? cand[lane +  0] : -3.0e38f;
        float c1 = (lane + 32 < n) ? cand[lane + 32] : -3.0e38f;
        float c2 = (lane + 64 < n) ? cand[lane + 64] : -3.0e38f;
        float c3 = (lane + 96 < n) ? cand[lane + 96] : -3.0e38f;

        float T = T0;
#pragma unroll 1
        for (int it = 0; it < 32; ++it) {
            float s = 0.0f, c = 0.0f;
            float d;
            d = c0 - T; if (d > 0.0f) { s += d; c += 1.0f; }
            d = c1 - T; if (d > 0.0f) { s += d; c += 1.0f; }
            d = c2 - T; if (d > 0.0f) { s += d; c += 1.0f; }
            d = c3 - T; if (d > 0.0f) { s += d; c += 1.0f; }
#pragma unroll
            for (int o = 16; o > 0; o >>= 1) {
                s += __shfl_xor_sync(0xFFFFFFFFu, s, o);
                c += __shfl_xor_sync(0xFFFFFFFFu, c, o);
            }
            if (c < 0.5f) break;           // degenerate (all-masked row)
            float delta = __fdividef(s - 1.0f, c);
            T += delta;
            if (fabsf(delta) < 1e-6f) break;
        }
        tau = T;
    } else {
        // ---- Fallback: proven block-Newton (block-uniform branch) ----
        __syncthreads();
        float T = T0;
#pragma unroll 1
        for (int it = 0; it < 32; ++it) {
            const int b = (it & 1) ^ 1;
            float s = 0.0f;
            int   c = 0;
#pragma unroll
            for (int e = 0; e < ELEMS; e++) {
                float d = z[e] - T;
                if (d > 0.0f) { s += d; c += 1; }
            }
#pragma unroll
            for (int o = 16; o > 0; o >>= 1) {
                s += __shfl_xor_sync(0xFFFFFFFFu, s, o);
                c += __shfl_xor_sync(0xFFFFFFFFu, c, o);
            }
            if (lane == 0) { shs[b][wid] = s; shc[b][wid] = c; }
            __syncthreads();
            float S = 0.0f;
            int   C = 0;
#pragma unroll
            for (int i = 0; i < NWARPS; i++) { S += shs[b][i]; C += shc[b][i]; }

            if (C == 0) break;
            float delta = __fdividef(S - 1.0f, (float)C);
            T += delta;
            if (fabsf(delta) < 1e-6f) break;
        }
        tau = T;
    }

    // ---- Output: relu(z - tau). Masked entries are ~-2e7, relu -> 0. ----
#pragma unroll
    for (int v = 0; v < VEC; v++) {
        float4 ov;
        ov.x = fmaxf(0.0f, z[v * 4 + 0] - tau);
        ov.y = fmaxf(0.0f, z[v * 4 + 1] - tau);
        ov.z = fmaxf(0.0f, z[v * 4 + 2] - tau);
        ov.w = fmaxf(0.0f, z[v * 4 + 3] - tau);
        orow[t + v * THREADS] = ov;
    }
}

extern "C" void kernel_launch(void* const* d_in, const int* in_sizes, int n_in,
                              void* d_out, int out_size) {
    const float* x = (const float*)d_in[0];
    const float* m = (const float*)d_in[1];
    float* out = (float*)d_out;
    sparsemax_kernel<<<ROWS, THREADS>>>(x, m, out);
}

// round 14
// speedup vs baseline: 1.0216x; 1.0103x over previous
#include <cuda_runtime.h>
#include <cuda_bf16.h>

// Sparsemax over rows: x, mask are [8192, 4096] fp32; out fp32 same shape.
// z = (mask ? x : NEG_BIG) * 2 ; tau solves sum(relu(z - tau)) = 1 ;
// out = relu(z - tau)  (mask multiply implied: masked z is hugely negative).
//
// R14 = R9 skeleton (best wall 62.6-62.8 us) with a slimmer warp-local
// Newton: CAP 128 -> 64 (2 candidate regs/lane; support is ~2-6 elems) and
// the support-count reduced via ballot+popc (2 ops, warp-uniform) instead of
// a 5-shuffle chain. Proven block-Newton fallback retained (block-uniform).

#define ROWS 8192
#define COLS 4096
#define THREADS 256
#define NWARPS (THREADS / 32)
#define ELEMS (COLS / THREADS)   // 16 floats per thread
#define VEC (ELEMS / 4)          // 4 float4 per thread
#define CAP 64                   // candidate buffer (2 per lane)

__global__ __launch_bounds__(THREADS, 5)
void sparsemax_kernel(const float* __restrict__ x,
                      const float* __restrict__ m,
                      float* __restrict__ out) {
    const int row = blockIdx.x;
    const int t   = threadIdx.x;
    const int lane = t & 31;
    const int wid  = t >> 5;

    const float4* __restrict__ xr = reinterpret_cast<const float4*>(x + (size_t)row * COLS);
    const float4* __restrict__ mr = reinterpret_cast<const float4*>(m + (size_t)row * COLS);
    float4* __restrict__ orow     = reinterpret_cast<float4*>(out + (size_t)row * COLS);

    __shared__ float shs[2][NWARPS];   // reduce scratch (max / fallback s)
    __shared__ int   shc[2][NWARPS];   // warp candidate counts / fallback c
    __shared__ float cand[CAP];        // gathered candidates

    // ---- Front-batch ALL loads (8 x LDG.128 in flight per thread) ----
    float4 xv[VEC];
    float4 mv[VEC];
#pragma unroll
    for (int v = 0; v < VEC; v++) xv[v] = xr[t + v * THREADS];
#pragma unroll
    for (int v = 0; v < VEC; v++) mv[v] = mr[t + v * THREADS];

    // ---- Apply mask + temperature, track local max ----
    float z[ELEMS];
    float vmax = -3.0e38f;
    const float NEGZ = -9999999.9f * 2.0f;  // masked value after temperature
#pragma unroll
    for (int v = 0; v < VEC; v++) {
        float z0 = (mv[v].x != 0.0f) ? (xv[v].x * 2.0f) : NEGZ;
        float z1 = (mv[v].y != 0.0f) ? (xv[v].y * 2.0f) : NEGZ;
        float z2 = (mv[v].z != 0.0f) ? (xv[v].z * 2.0f) : NEGZ;
        float z3 = (mv[v].w != 0.0f) ? (xv[v].w * 2.0f) : NEGZ;
        z[v * 4 + 0] = z0;
        z[v * 4 + 1] = z1;
        z[v * 4 + 2] = z2;
        z[v * 4 + 3] = z3;
        vmax = fmaxf(vmax, fmaxf(fmaxf(z0, z1), fmaxf(z2, z3)));
    }

    // ---- Block max reduction ----
#pragma unroll
    for (int o = 16; o > 0; o >>= 1)
        vmax = fmaxf(vmax, __shfl_xor_sync(0xFFFFFFFFu, vmax, o));
    if (lane == 0) shs[0][wid] = vmax;
    __syncthreads();                       // barrier 1
    float zmax = -3.0e38f;
#pragma unroll
    for (int i = 0; i < NWARPS; i++) zmax = fmaxf(zmax, shs[0][i]);

    const float T0 = zmax - 1.0f;

    // ---- Count candidates (z > T0) per thread; deterministic warp scan ----
    int lc = 0;
#pragma unroll
    for (int e = 0; e < ELEMS; e++) lc += (z[e] > T0) ? 1 : 0;

    int inc = lc;                          // inclusive prefix over lanes
#pragma unroll
    for (int o = 1; o < 32; o <<= 1) {
        int v = __shfl_up_sync(0xFFFFFFFFu, inc, o);
        if (lane >= o) inc += v;
    }
    const int excl = inc - lc;
    const int wtot = __shfl_sync(0xFFFFFFFFu, inc, 31);
    if (lane == 31) shc[1][wid] = wtot;
    __syncthreads();                       // barrier 2

    int base = 0, n = 0;
#pragma unroll
    for (int i = 0; i < NWARPS; i++) {
        int w = shc[1][i];
        if (i < wid) base += w;
        n += w;
    }

    float tau;
    if (n <= CAP) {
        // ---- Write candidates at deterministic slots ----
        int off = base + excl;
#pragma unroll
        for (int e = 0; e < ELEMS; e++) {
            if (z[e] > T0) cand[off++] = z[e];
        }
        __syncthreads();                   // barrier 3 (last barrier)

        // ---- Warp-local Newton (every warp redundantly; identical tau) ----
        float c0 = (lane +  0 < n) ? cand[lane +  0] : -3.0e38f;
        float c1 = (lane + 32 < n) ? cand[lane + 32] : -3.0e38f;

        float T = T0;
#pragma unroll 1
        for (int it = 0; it < 32; ++it) {
            float d0 = c0 - T;
            float d1 = c1 - T;
            float s = 0.0f;
            if (d0 > 0.0f) s += d0;
            if (d1 > 0.0f) s += d1;
            // Count via ballots: warp-uniform, no shuffle chain.
            int c = __popc(__ballot_sync(0xFFFFFFFFu, d0 > 0.0f))
                  + __popc(__ballot_sync(0xFFFFFFFFu, d1 > 0.0f));
#pragma unroll
            for (int o = 16; o > 0; o >>= 1)
                s += __shfl_xor_sync(0xFFFFFFFFu, s, o);
            if (c == 0) break;             // degenerate (all-masked row)
            float delta = __fdividef(s - 1.0f, (float)c);
            T += delta;
            if (fabsf(delta) < 1e-6f) break;
        }
        tau = T;
    } else {
        // ---- Fallback: proven block-Newton (block-uniform branch) ----
        __syncthreads();
        float T = T0;
#pragma unroll 1
        for (int it = 0; it < 32; ++it) {
            const int b = (it & 1) ^ 1;
            float s = 0.0f;
            int   c = 0;
#pragma unroll
            for (int e = 0; e < ELEMS; e++) {
                float d = z[e] - T;
                if (d > 0.0f) { s += d; c += 1; }
            }
#pragma unroll
            for (int o = 16; o > 0; o >>= 1) {
                s += __shfl_xor_sync(0xFFFFFFFFu, s, o);
                c += __shfl_xor_sync(0xFFFFFFFFu, c, o);
            }
            if (lane == 0) { shs[b][wid] = s; shc[b][wid] = c; }
            __syncthreads();
            float S = 0.0f;
            int   C = 0;
#pragma unroll
            for (int i = 0; i < NWARPS; i++) { S += shs[b][i]; C += shc[b][i]; }

            if (C == 0) break;
            float delta = __fdividef(S - 1.0f, (float)C);
            T += delta;
            if (fabsf(delta) < 1e-6f) break;
        }
        tau = T;
    }

    // ---- Output: relu(z - tau). Masked entries are ~-2e7, relu -> 0. ----
#pragma unroll
    for (int v = 0; v < VEC; v++) {
        float4 ov;
        ov.x = fmaxf(0.0f, z[v * 4 + 0] - tau);
        ov.y = fmaxf(0.0f, z[v * 4 + 1] - tau);
        ov.z = fmaxf(0.0f, z[v * 4 + 2] - tau);
        ov.w = fmaxf(0.0f, z[v * 4 + 3] - tau);
        orow[t + v * THREADS] = ov;
    }
}

extern "C" void kernel_launch(void* const* d_in, const int* in_sizes, int n_in,
                              void* d_out, int out_size) {
    const float* x = (const float*)d_in[0];
    const float* m = (const float*)d_in[1];
    float* out = (float*)d_out;
    sparsemax_kernel<<<ROWS, THREADS>>>(x, m, out);
}